// round 6
// baseline (speedup 1.0000x reference)
#include <cuda_runtime.h>
#include <math.h>
#include <stdint.h>

#define H  1024
#define B  64
#define L  1024
#define VP 32000
#define VC 32000
#define LSPLIT 16

// ---- GEMM config (shared by generic + logits kernels) ----
#define TV   128          // rows per block (M)
#define KC   16           // k per smem tile
#define WROW 136          // padded W tile row (floats)
#define XROW 72           // padded X tile row
#define WT_FLOATS (2 * 2 * KC * WROW)
#define XT_FLOATS (2 * 2 * KC * XROW)
#define SM_TOTAL  ((WT_FLOATS + XT_FLOATS) * 4)

// ---- scratch ----
__device__ __align__(16) float g_xh[2 * B * H];      // [0]=x(embedded), [1]=h_prev
__device__ __align__(16) float g_gates[6 * H * B];   // [row][b], rows: ir,iz,in,hr,hz,hn
__device__ __align__(16) float g_hnew[B * H];
__device__ __align__(16) float g_hc[B * 2 * H];      // [b][ h_new | ctx ]
__device__ __align__(16) float g_scores[B * L];
__device__ __align__(16) float g_attn[B * L];
__device__ __align__(16) float g_ctxpart[B * LSPLIT * H];
__device__ __align__(16) float g_concat[B * H];      // [b][k]

__device__ __forceinline__ float warp_sum(float v) {
#pragma unroll
    for (int o = 16; o; o >>= 1) v += __shfl_xor_sync(0xffffffffu, v, o);
    return v;
}
__device__ __forceinline__ uint32_t f2tf32(float x) {
    uint32_t u; asm("cvt.rna.tf32.f32 %0, %1;" : "=r"(u) : "f"(x)); return u;
}
__device__ __forceinline__ void mma_tf32(float* c, const uint32_t* a,
                                         uint32_t b0, uint32_t b1) {
    asm volatile(
        "mma.sync.aligned.m16n8k8.row.col.f32.tf32.tf32.f32 "
        "{%0,%1,%2,%3}, {%4,%5,%6,%7}, {%8,%9}, {%0,%1,%2,%3};"
        : "+f"(c[0]), "+f"(c[1]), "+f"(c[2]), "+f"(c[3])
        : "r"(a[0]), "r"(a[1]), "r"(a[2]), "r"(a[3]), "r"(b0), "r"(b1));
}

// ---------------------------------------------------------------------------
// 0) pack x (embedding gather) and h_prev into g_xh
// ---------------------------------------------------------------------------
__global__ void pack_xh_kernel(const int* __restrict__ seq,
                               const float* __restrict__ hprev,
                               const float* __restrict__ emb) {
    int b = blockIdx.x, tid = threadIdx.x;    // 256 threads, float4
    const float4* xr = (const float4*)(emb + (size_t)seq[b] * H);
    const float4* hr = (const float4*)(hprev + (size_t)b * H);
    ((float4*)(g_xh + (size_t)b * H))[tid] = xr[tid];
    ((float4*)(g_xh + (size_t)(B + b) * H))[tid] = hr[tid];
}

// ---------------------------------------------------------------------------
// Generic split-tf32 MMA GEMM: out[row][b] (+epilogue) = sum_k A[row][k]*X[b][k]
// Block = 128 rows x 64 batch, 8 warps (4Mx2N), warp tile 32x32,
// KC=16 double-buffered smem with register prefetch.
// op 0: raw store to outp[(v0+row)*64 + b]   (gates; A/X selected per half)
// op 1: tanh(acc + bias[row]) -> g_concat[b*H + row]
// ---------------------------------------------------------------------------
__global__ __launch_bounds__(256) void gemm_tf32(
        const float* __restrict__ A0, const float* __restrict__ A1,
        const float* __restrict__ X0, const float* __restrict__ X1,
        float* __restrict__ outp, const float* __restrict__ bias,
        int K, int halfBlocks, int op) {
    extern __shared__ float smf[];
    float* Wt = smf;
    float* Xt = smf + WT_FLOATS;

    int tid = threadIdx.x;
    int wid = tid >> 5, lane = tid & 31;
    int grp = lane >> 2, tig = lane & 3;
    int warpM = wid & 3, warpN = wid >> 2;

    const float* A = A0; const float* X = X0;
    int blk = blockIdx.x;
    size_t outOff = 0;
    if (halfBlocks > 0 && blk >= halfBlocks) {
        A = A1; X = X1; blk -= halfBlocks;
        outOff = (size_t)halfBlocks * TV * B;
    }
    int v0 = blk * TV;
    int NKT = K / KC;

#define WT_(buf, part, k, v) Wt[(((buf) * 2 + (part)) * KC + (k)) * WROW + (v)]
#define XT_(buf, part, k, b) Xt[(((buf) * 2 + (part)) * KC + (k)) * XROW + (b)]

    float acc[2][4][4];
#pragma unroll
    for (int i = 0; i < 2; i++)
#pragma unroll
        for (int j = 0; j < 4; j++)
#pragma unroll
            for (int q = 0; q < 4; q++) acc[i][j][q] = 0.f;

    int wv0 = tid >> 2, wkq = tid & 3;
    int xb = tid >> 2, xkq = tid & 3;

    // prime buffer 0
    {
#pragma unroll
        for (int r = 0; r < 2; r++) {
            int v = wv0 + r * 64;
            float4 w4 = *(const float4*)(A + (size_t)(v0 + v) * K + wkq * 4);
            float wv[4] = {w4.x, w4.y, w4.z, w4.w};
#pragma unroll
            for (int j = 0; j < 4; j++) {
                float hf = __uint_as_float(f2tf32(wv[j]));
                WT_(0, 0, wkq * 4 + j, v) = hf;
                WT_(0, 1, wkq * 4 + j, v) = __uint_as_float(f2tf32(wv[j] - hf));
            }
        }
        float4 x4 = *(const float4*)(X + (size_t)xb * K + xkq * 4);
        float xv[4] = {x4.x, x4.y, x4.z, x4.w};
#pragma unroll
        for (int j = 0; j < 4; j++) {
            float hf = __uint_as_float(f2tf32(xv[j]));
            XT_(0, 0, xkq * 4 + j, xb) = hf;
            XT_(0, 1, xkq * 4 + j, xb) = __uint_as_float(f2tf32(xv[j] - hf));
        }
    }
    __syncthreads();

    for (int t = 0; t < NKT; t++) {
        int cur = t & 1;
        float4 wpre[2], xpre;
        if (t + 1 < NKT) {
            int kc = (t + 1) * KC;
#pragma unroll
            for (int r = 0; r < 2; r++)
                wpre[r] = *(const float4*)(A + (size_t)(v0 + wv0 + r * 64) * K + kc + wkq * 4);
            xpre = *(const float4*)(X + (size_t)xb * K + kc + xkq * 4);
        }
#pragma unroll
        for (int ks = 0; ks < KC / 8; ks++) {
            int k0 = ks * 8 + tig;
            uint32_t aH[2][4], aL[2][4];
#pragma unroll
            for (int mf = 0; mf < 2; mf++) {
                int m = warpM * 32 + mf * 16 + grp;
                aH[mf][0] = __float_as_uint(WT_(cur, 0, k0, m));
                aH[mf][1] = __float_as_uint(WT_(cur, 0, k0, m + 8));
                aH[mf][2] = __float_as_uint(WT_(cur, 0, k0 + 4, m));
                aH[mf][3] = __float_as_uint(WT_(cur, 0, k0 + 4, m + 8));
                aL[mf][0] = __float_as_uint(WT_(cur, 1, k0, m));
                aL[mf][1] = __float_as_uint(WT_(cur, 1, k0, m + 8));
                aL[mf][2] = __float_as_uint(WT_(cur, 1, k0 + 4, m));
                aL[mf][3] = __float_as_uint(WT_(cur, 1, k0 + 4, m + 8));
            }
#pragma unroll
            for (int nf = 0; nf < 4; nf++) {
                int n = warpN * 32 + nf * 8 + grp;
                uint32_t bH0 = __float_as_uint(XT_(cur, 0, k0, n));
                uint32_t bH1 = __float_as_uint(XT_(cur, 0, k0 + 4, n));
                uint32_t bL0 = __float_as_uint(XT_(cur, 1, k0, n));
                uint32_t bL1 = __float_as_uint(XT_(cur, 1, k0 + 4, n));
#pragma unroll
                for (int mf = 0; mf < 2; mf++) {
                    mma_tf32(acc[mf][nf], aH[mf], bH0, bH1);
                    mma_tf32(acc[mf][nf], aH[mf], bL0, bL1);
                    mma_tf32(acc[mf][nf], aL[mf], bH0, bH1);
                }
            }
        }
        if (t + 1 < NKT) {
            int nxt = cur ^ 1;
#pragma unroll
            for (int r = 0; r < 2; r++) {
                int v = wv0 + r * 64;
                float wv[4] = {wpre[r].x, wpre[r].y, wpre[r].z, wpre[r].w};
#pragma unroll
                for (int j = 0; j < 4; j++) {
                    float hf = __uint_as_float(f2tf32(wv[j]));
                    WT_(nxt, 0, wkq * 4 + j, v) = hf;
                    WT_(nxt, 1, wkq * 4 + j, v) = __uint_as_float(f2tf32(wv[j] - hf));
                }
            }
            float xv[4] = {xpre.x, xpre.y, xpre.z, xpre.w};
#pragma unroll
            for (int j = 0; j < 4; j++) {
                float hf = __uint_as_float(f2tf32(xv[j]));
                XT_(nxt, 0, xkq * 4 + j, xb) = hf;
                XT_(nxt, 1, xkq * 4 + j, xb) = __uint_as_float(f2tf32(xv[j] - hf));
            }
        }
        __syncthreads();
    }

    // epilogue
#pragma unroll
    for (int mf = 0; mf < 2; mf++) {
        int vr = v0 + warpM * 32 + mf * 16 + grp;   // global row (within half)
#pragma unroll
        for (int nf = 0; nf < 4; nf++) {
            int bcol = warpN * 32 + nf * 8 + 2 * tig;
            if (op == 0) {
                float* o = outp + outOff;
                o[(size_t)vr * B + bcol]           = acc[mf][nf][0];
                o[(size_t)vr * B + bcol + 1]       = acc[mf][nf][1];
                o[(size_t)(vr + 8) * B + bcol]     = acc[mf][nf][2];
                o[(size_t)(vr + 8) * B + bcol + 1] = acc[mf][nf][3];
            } else {
                float b0 = bias[vr], b1 = bias[vr + 8];
                g_concat[(size_t)bcol * H + vr]           = tanhf(acc[mf][nf][0] + b0);
                g_concat[(size_t)(bcol + 1) * H + vr]     = tanhf(acc[mf][nf][1] + b0);
                g_concat[(size_t)bcol * H + vr + 8]       = tanhf(acc[mf][nf][2] + b1);
                g_concat[(size_t)(bcol + 1) * H + vr + 8] = tanhf(acc[mf][nf][3] + b1);
            }
        }
    }
#undef WT_
#undef XT_
}

// ---------------------------------------------------------------------------
// gate elementwise: combine gi/gh + biases -> h_new
// ---------------------------------------------------------------------------
__global__ void gru_gate_kernel(const float* __restrict__ hprev,
                                const float* __restrict__ b_ih,
                                const float* __restrict__ b_hh,
                                float* __restrict__ hidden_out) {
    int tid = threadIdx.x;
    int b = tid & 63;
    int i = blockIdx.x * 4 + (tid >> 6);
    float gir = g_gates[(size_t)i * B + b];
    float giz = g_gates[(size_t)(H + i) * B + b];
    float gin = g_gates[(size_t)(2 * H + i) * B + b];
    float ghr = g_gates[(size_t)(3 * H + i) * B + b];
    float ghz = g_gates[(size_t)(4 * H + i) * B + b];
    float ghn = g_gates[(size_t)(5 * H + i) * B + b];
    float r = 1.f / (1.f + expf(-(gir + b_ih[i] + ghr + b_hh[i])));
    float z = 1.f / (1.f + expf(-(giz + b_ih[H + i] + ghz + b_hh[H + i])));
    float n = tanhf(gin + b_ih[2 * H + i] + r * (ghn + b_hh[2 * H + i]));
    float hv = hprev[(size_t)b * H + i];
    float hn = (1.f - z) * n + z * hv;
    g_hnew[(size_t)b * H + i] = hn;
    g_hc[(size_t)b * 2 * H + i] = hn;
    hidden_out[(size_t)b * H + i] = hn;
}

// ---------------------------------------------------------------------------
// scores[b][l] = h_new[b] . enc[l][b]
// ---------------------------------------------------------------------------
__global__ void scores_kernel(const float* __restrict__ enc) {
    int l = blockIdx.x;
    int wid = threadIdx.x >> 5, lane = threadIdx.x & 31;
    const float4* encl = (const float4*)(enc + (size_t)l * B * H);
#pragma unroll
    for (int t = 0; t < 8; t++) {
        int b = wid + 8 * t;
        const float4* er = encl + (size_t)b * (H / 4);
        const float4* hr = (const float4*)g_hnew + (size_t)b * (H / 4);
        float s = 0.f;
        for (int k = lane; k < H / 4; k += 32) {
            float4 e = er[k], h = hr[k];
            s += e.x * h.x + e.y * h.y + e.z * h.z + e.w * h.w;
        }
        s = warp_sum(s);
        if (lane == 0) g_scores[b * L + l] = s;
    }
}

// ---------------------------------------------------------------------------
// softmax
// ---------------------------------------------------------------------------
__global__ void softmax_kernel(float* __restrict__ attn_out) {
    int b = blockIdx.x, tid = threadIdx.x;
    __shared__ float sh[8];
    __shared__ float sval;
    float m = -1e30f;
    for (int l = tid; l < L; l += 256) m = fmaxf(m, g_scores[b * L + l]);
#pragma unroll
    for (int o = 16; o; o >>= 1) m = fmaxf(m, __shfl_xor_sync(0xffffffffu, m, o));
    if ((tid & 31) == 0) sh[tid >> 5] = m;
    __syncthreads();
    if (tid == 0) {
        float mm = sh[0];
        for (int j = 1; j < 8; j++) mm = fmaxf(mm, sh[j]);
        sval = mm;
    }
    __syncthreads();
    m = sval;
    float s = 0.f;
    for (int l = tid; l < L; l += 256) s += expf(g_scores[b * L + l] - m);
    s = warp_sum(s);
    __syncthreads();
    if ((tid & 31) == 0) sh[tid >> 5] = s;
    __syncthreads();
    if (tid == 0) {
        float ss = 0.f;
        for (int j = 0; j < 8; j++) ss += sh[j];
        sval = ss;
    }
    __syncthreads();
    float inv = 1.f / sval;
    for (int l = tid; l < L; l += 256) {
        float w = expf(g_scores[b * L + l] - m) * inv;
        g_attn[b * L + l] = w;
        attn_out[b * L + l] = w;
    }
}

// ---------------------------------------------------------------------------
// context partials + reduce (reduce writes into g_hc[:,H:2H])
// ---------------------------------------------------------------------------
__global__ void ctx_part_kernel(const float* __restrict__ enc) {
    int b = blockIdx.x, c = blockIdx.y;
    int tid = threadIdx.x;
    float4 a = make_float4(0.f, 0.f, 0.f, 0.f);
    int l0 = c * (L / LSPLIT);
    for (int j = 0; j < L / LSPLIT; j++) {
        int l = l0 + j;
        float w = g_attn[b * L + l];
        float4 e = ((const float4*)(enc + (size_t)l * B * H + (size_t)b * H))[tid];
        a.x += w * e.x; a.y += w * e.y; a.z += w * e.z; a.w += w * e.w;
    }
    ((float4*)(g_ctxpart + ((size_t)(b * LSPLIT + c)) * H))[tid] = a;
}

__global__ void ctx_reduce_kernel() {
    int b = blockIdx.x, tid = threadIdx.x;
    float4 s = make_float4(0.f, 0.f, 0.f, 0.f);
#pragma unroll
    for (int c = 0; c < LSPLIT; c++) {
        float4 p = ((const float4*)(g_ctxpart + ((size_t)(b * LSPLIT + c)) * H))[tid];
        s.x += p.x; s.y += p.y; s.z += p.z; s.w += p.w;
    }
    ((float4*)(g_hc + (size_t)b * 2 * H + H))[tid] = s;
}

// ---------------------------------------------------------------------------
// logits: split-tf32 mma.sync GEMM (unchanged from R5)
// ---------------------------------------------------------------------------
__global__ __launch_bounds__(256) void logits_mma(
        const float* __restrict__ wp, const float* __restrict__ bp,
        const float* __restrict__ wc, const float* __restrict__ bc,
        float* __restrict__ out) {
    extern __shared__ float smf[];
    float* Wt = smf;
    float* Xt = smf + WT_FLOATS;

    int tid = threadIdx.x;
    int wid = tid >> 5, lane = tid & 31;
    int grp = lane >> 2, tig = lane & 3;
    int warpM = wid & 3, warpN = wid >> 2;

    int v0 = blockIdx.x * TV;
    const float* W; const float* bias; float* obase;
    if (v0 < VP) { W = wp; bias = bp; obase = out; }
    else { W = wc; bias = bc; obase = out + (size_t)B * VP; v0 -= VP; }

#define WT(buf, part, k, v) Wt[(((buf) * 2 + (part)) * KC + (k)) * WROW + (v)]
#define XT(buf, part, k, b) Xt[(((buf) * 2 + (part)) * KC + (k)) * XROW + (b)]

    float acc[2][4][4];
#pragma unroll
    for (int i = 0; i < 2; i++)
#pragma unroll
        for (int j = 0; j < 4; j++)
#pragma unroll
            for (int q = 0; q < 4; q++) acc[i][j][q] = 0.f;

    int wv0 = tid >> 2, wkq = tid & 3;
    int xb = tid >> 2, xkq = tid & 3;

    {
#pragma unroll
        for (int r = 0; r < 2; r++) {
            int v = wv0 + r * 64;
            float4 w4 = *(const float4*)(W + (size_t)(v0 + v) * H + wkq * 4);
            float wv[4] = {w4.x, w4.y, w4.z, w4.w};
#pragma unroll
            for (int j = 0; j < 4; j++) {
                float hf = __uint_as_float(f2tf32(wv[j]));
                WT(0, 0, wkq * 4 + j, v) = hf;
                WT(0, 1, wkq * 4 + j, v) = __uint_as_float(f2tf32(wv[j] - hf));
            }
        }
        float4 x4 = *(const float4*)(g_concat + (size_t)xb * H + xkq * 4);
        float xv[4] = {x4.x, x4.y, x4.z, x4.w};
#pragma unroll
        for (int j = 0; j < 4; j++) {
            float hf = __uint_as_float(f2tf32(xv[j]));
            XT(0, 0, xkq * 4 + j, xb) = hf;
            XT(0, 1, xkq * 4 + j, xb) = __uint_as_float(f2tf32(xv[j] - hf));
        }
    }
    __syncthreads();

    const int NKT_L = H / KC;
    for (int t = 0; t < NKT_L; t++) {
        int cur = t & 1;
        float4 wpre[2], xpre;
        if (t + 1 < NKT_L) {
            int kc = (t + 1) * KC;
#pragma unroll
            for (int r = 0; r < 2; r++)
                wpre[r] = *(const float4*)(W + (size_t)(v0 + wv0 + r * 64) * H + kc + wkq * 4);
            xpre = *(const float4*)(g_concat + (size_t)xb * H + kc + xkq * 4);
        }
#pragma unroll
        for (int ks = 0; ks < KC / 8; ks++) {
            int k0 = ks * 8 + tig;
            uint32_t aH[2][4], aL[2][4];
#pragma unroll
            for (int mf = 0; mf < 2; mf++) {
                int m = warpM * 32 + mf * 16 + grp;
                aH[mf][0] = __float_as_uint(WT(cur, 0, k0, m));
                aH[mf][1] = __float_as_uint(WT(cur, 0, k0, m + 8));
                aH[mf][2] = __float_as_uint(WT(cur, 0, k0 + 4, m));
                aH[mf][3] = __float_as_uint(WT(cur, 0, k0 + 4, m + 8));
                aL[mf][0] = __float_as_uint(WT(cur, 1, k0, m));
                aL[mf][1] = __float_as_uint(WT(cur, 1, k0, m + 8));
                aL[mf][2] = __float_as_uint(WT(cur, 1, k0 + 4, m));
                aL[mf][3] = __float_as_uint(WT(cur, 1, k0 + 4, m + 8));
            }
#pragma unroll
            for (int nf = 0; nf < 4; nf++) {
                int n = warpN * 32 + nf * 8 + grp;
                uint32_t bH0 = __float_as_uint(XT(cur, 0, k0, n));
                uint32_t bH1 = __float_as_uint(XT(cur, 0, k0 + 4, n));
                uint32_t bL0 = __float_as_uint(XT(cur, 1, k0, n));
                uint32_t bL1 = __float_as_uint(XT(cur, 1, k0 + 4, n));
#pragma unroll
                for (int mf = 0; mf < 2; mf++) {
                    mma_tf32(acc[mf][nf], aH[mf], bH0, bH1);
                    mma_tf32(acc[mf][nf], aH[mf], bL0, bL1);
                    mma_tf32(acc[mf][nf], aL[mf], bH0, bH1);
                }
            }
        }
        if (t + 1 < NKT_L) {
            int nxt = cur ^ 1;
#pragma unroll
            for (int r = 0; r < 2; r++) {
                int v = wv0 + r * 64;
                float wv[4] = {wpre[r].x, wpre[r].y, wpre[r].z, wpre[r].w};
#pragma unroll
                for (int j = 0; j < 4; j++) {
                    float hf = __uint_as_float(f2tf32(wv[j]));
                    WT(nxt, 0, wkq * 4 + j, v) = hf;
                    WT(nxt, 1, wkq * 4 + j, v) = __uint_as_float(f2tf32(wv[j] - hf));
                }
            }
            float xv[4] = {xpre.x, xpre.y, xpre.z, xpre.w};
#pragma unroll
            for (int j = 0; j < 4; j++) {
                float hf = __uint_as_float(f2tf32(xv[j]));
                XT(nxt, 0, xkq * 4 + j, xb) = hf;
                XT(nxt, 1, xkq * 4 + j, xb) = __uint_as_float(f2tf32(xv[j] - hf));
            }
        }
        __syncthreads();
    }

#pragma unroll
    for (int mf = 0; mf < 2; mf++) {
        int vr = v0 + warpM * 32 + mf * 16 + grp;
        float b0 = bias[vr], b1 = bias[vr + 8];
#pragma unroll
        for (int nf = 0; nf < 4; nf++) {
            int bcol = warpN * 32 + nf * 8 + 2 * tig;
            obase[(size_t)bcol * VP + vr]           = acc[mf][nf][0] + b0;
            obase[(size_t)(bcol + 1) * VP + vr]     = acc[mf][nf][1] + b0;
            obase[(size_t)bcol * VP + vr + 8]       = acc[mf][nf][2] + b1;
            obase[(size_t)(bcol + 1) * VP + vr + 8] = acc[mf][nf][3] + b1;
        }
    }
#undef WT
#undef XT
}

// ---------------------------------------------------------------------------
extern "C" void kernel_launch(void* const* d_in, const int* in_sizes, int n_in,
                              void* d_out, int out_size) {
    const int*   seq         = (const int*)d_in[0];
    const float* last_hidden = (const float*)d_in[1];
    const float* enc         = (const float*)d_in[2];
    const float* emb         = (const float*)d_in[3];
    const float* w_ih        = (const float*)d_in[4];
    const float* w_hh        = (const float*)d_in[5];
    const float* b_ih        = (const float*)d_in[6];
    const float* b_hh        = (const float*)d_in[7];
    const float* concat_w    = (const float*)d_in[8];
    const float* concat_b    = (const float*)d_in[9];
    const float* owp         = (const float*)d_in[10];
    const float* obp         = (const float*)d_in[11];
    const float* owc         = (const float*)d_in[12];
    const float* obc         = (const float*)d_in[13];

    float* out        = (float*)d_out;
    float* out_hidden = out + (size_t)B * (VP + VC);   // [1,B,H]
    float* out_attn   = out_hidden + (size_t)B * H;    // [B,1,L]

    cudaFuncSetAttribute(gemm_tf32, cudaFuncAttributeMaxDynamicSharedMemorySize, SM_TOTAL);
    cudaFuncSetAttribute(logits_mma, cudaFuncAttributeMaxDynamicSharedMemorySize, SM_TOTAL);

    float* g_gates_p; cudaGetSymbolAddress((void**)&g_gates_p, g_gates);
    float* g_xh_p;    cudaGetSymbolAddress((void**)&g_xh_p, g_xh);
    float* g_hc_p;    cudaGetSymbolAddress((void**)&g_hc_p, g_hc);

    pack_xh_kernel<<<B, 256>>>(seq, last_hidden, emb);
    // gates: blocks 0-23 -> w_ih x, 24-47 -> w_hh h
    gemm_tf32<<<48, 256, SM_TOTAL>>>(w_ih, w_hh, g_xh_p, g_xh_p + (size_t)B * H,
                                     g_gates_p, nullptr, H, 24, 0);
    gru_gate_kernel<<<H / 4, 256>>>(last_hidden, b_ih, b_hh, out_hidden);
    scores_kernel<<<L, 256>>>(enc);
    softmax_kernel<<<B, 256>>>(out_attn);
    ctx_part_kernel<<<dim3(B, LSPLIT), 256>>>(enc);
    ctx_reduce_kernel<<<B, 256>>>();
    // concat: tanh epilogue -> g_concat
    gemm_tf32<<<H / TV, 256, SM_TOTAL>>>(concat_w, nullptr, g_hc_p, nullptr,
                                         nullptr, concat_b, 2 * H, 0, 1);
    logits_mma<<<(VP + VC) / TV, 256, SM_TOTAL>>>(owp, obp, owc, obc, out);
}

// round 7
// speedup vs baseline: 1.4889x; 1.4889x over previous
#include <cuda_runtime.h>
#include <math.h>
#include <stdint.h>

#define H  1024
#define B  64
#define L  1024
#define VP 32000
#define VC 32000
#define LSPLIT 16

// ---- logits tf32 GEMM config ----
#define TVL   128         // vocab rows per block
#define KCL   16          // k per tile
#define NKTL  (H / KCL)   // 64 tiles
#define PITCH 20          // padded row pitch (floats) — conflict-free frags

// ---- scratch ----
__device__ __align__(16) float g_hnew[B * H];
__device__ __align__(16) float g_scores[B * L];
__device__ __align__(16) float g_attn[B * L];
__device__ __align__(16) float g_ctxpart[B * LSPLIT * H];
__device__ __align__(16) float g_ctx[B * H];
__device__ __align__(16) float g_concat[B * H];   // [b][k]

__device__ __forceinline__ float warp_sum(float v) {
#pragma unroll
    for (int o = 16; o; o >>= 1) v += __shfl_xor_sync(0xffffffffu, v, o);
    return v;
}
__device__ __forceinline__ float f2tf32f(float x) {
    uint32_t u; asm("cvt.rna.tf32.f32 %0, %1;" : "=r"(u) : "f"(x));
    return __uint_as_float(u);
}
__device__ __forceinline__ void mma_tf32(float* c, const uint32_t* a,
                                         uint32_t b0, uint32_t b1) {
    asm volatile(
        "mma.sync.aligned.m16n8k8.row.col.f32.tf32.tf32.f32 "
        "{%0,%1,%2,%3}, {%4,%5,%6,%7}, {%8,%9}, {%0,%1,%2,%3};"
        : "+f"(c[0]), "+f"(c[1]), "+f"(c[2]), "+f"(c[3])
        : "r"(a[0]), "r"(a[1]), "r"(a[2]), "r"(a[3]), "r"(b0), "r"(b1));
}

// ---------------------------------------------------------------------------
// 1) Fused GRU step (R2/R5 version — measured good)
// ---------------------------------------------------------------------------
__global__ void gru_kernel(const int* __restrict__ seq,
                           const float* __restrict__ hprev,
                           const float* __restrict__ emb,
                           const float* __restrict__ w_ih,
                           const float* __restrict__ w_hh,
                           const float* __restrict__ b_ih,
                           const float* __restrict__ b_hh,
                           float* __restrict__ hidden_out) {
    int i = blockIdx.x;
    __shared__ float sw[6][H];
    for (int k = threadIdx.x; k < H; k += blockDim.x) {
        sw[0][k] = w_ih[(size_t)i * H + k];
        sw[1][k] = w_ih[(size_t)(i + H) * H + k];
        sw[2][k] = w_ih[(size_t)(i + 2 * H) * H + k];
        sw[3][k] = w_hh[(size_t)i * H + k];
        sw[4][k] = w_hh[(size_t)(i + H) * H + k];
        sw[5][k] = w_hh[(size_t)(i + 2 * H) * H + k];
    }
    __syncthreads();
    int wid = threadIdx.x >> 5, lane = threadIdx.x & 31;
#pragma unroll
    for (int t = 0; t < 8; t++) {
        int b = wid + 8 * t;
        const float* xr = emb + (size_t)seq[b] * H;
        const float* hr = hprev + (size_t)b * H;
        float sir = 0.f, siz = 0.f, sin_ = 0.f, shr = 0.f, shz = 0.f, shn = 0.f;
        for (int k = lane; k < H; k += 32) {
            float xv = xr[k], hv = hr[k];
            sir += xv * sw[0][k]; siz += xv * sw[1][k]; sin_ += xv * sw[2][k];
            shr += hv * sw[3][k]; shz += hv * sw[4][k]; shn += hv * sw[5][k];
        }
        sir = warp_sum(sir); siz = warp_sum(siz); sin_ = warp_sum(sin_);
        shr = warp_sum(shr); shz = warp_sum(shz); shn = warp_sum(shn);
        if (lane == 0) {
            float gr = sir + b_ih[i] + shr + b_hh[i];
            float gz = siz + b_ih[i + H] + shz + b_hh[i + H];
            float r = 1.f / (1.f + expf(-gr));
            float z = 1.f / (1.f + expf(-gz));
            float n = tanhf(sin_ + b_ih[i + 2 * H] + r * (shn + b_hh[i + 2 * H]));
            float hv = hprev[(size_t)b * H + i];
            float hn = (1.f - z) * n + z * hv;
            g_hnew[b * H + i] = hn;
            hidden_out[b * H + i] = hn;
        }
    }
}

// ---------------------------------------------------------------------------
// 2) scores
// ---------------------------------------------------------------------------
__global__ void scores_kernel(const float* __restrict__ enc) {
    int l = blockIdx.x;
    int wid = threadIdx.x >> 5, lane = threadIdx.x & 31;
    const float4* encl = (const float4*)(enc + (size_t)l * B * H);
#pragma unroll
    for (int t = 0; t < 8; t++) {
        int b = wid + 8 * t;
        const float4* er = encl + (size_t)b * (H / 4);
        const float4* hr = (const float4*)g_hnew + (size_t)b * (H / 4);
        float s = 0.f;
        for (int k = lane; k < H / 4; k += 32) {
            float4 e = er[k], h = hr[k];
            s += e.x * h.x + e.y * h.y + e.z * h.z + e.w * h.w;
        }
        s = warp_sum(s);
        if (lane == 0) g_scores[b * L + l] = s;
    }
}

// ---------------------------------------------------------------------------
// 3) softmax
// ---------------------------------------------------------------------------
__global__ void softmax_kernel(float* __restrict__ attn_out) {
    int b = blockIdx.x, tid = threadIdx.x;
    __shared__ float sh[8];
    __shared__ float sval;
    float m = -1e30f;
    for (int l = tid; l < L; l += 256) m = fmaxf(m, g_scores[b * L + l]);
#pragma unroll
    for (int o = 16; o; o >>= 1) m = fmaxf(m, __shfl_xor_sync(0xffffffffu, m, o));
    if ((tid & 31) == 0) sh[tid >> 5] = m;
    __syncthreads();
    if (tid == 0) {
        float mm = sh[0];
        for (int j = 1; j < 8; j++) mm = fmaxf(mm, sh[j]);
        sval = mm;
    }
    __syncthreads();
    m = sval;
    float s = 0.f;
    for (int l = tid; l < L; l += 256) s += expf(g_scores[b * L + l] - m);
    s = warp_sum(s);
    __syncthreads();
    if ((tid & 31) == 0) sh[tid >> 5] = s;
    __syncthreads();
    if (tid == 0) {
        float ss = 0.f;
        for (int j = 0; j < 8; j++) ss += sh[j];
        sval = ss;
    }
    __syncthreads();
    float inv = 1.f / sval;
    for (int l = tid; l < L; l += 256) {
        float w = expf(g_scores[b * L + l] - m) * inv;
        g_attn[b * L + l] = w;
        attn_out[b * L + l] = w;
    }
}

// ---------------------------------------------------------------------------
// 4) context partials + reduce
// ---------------------------------------------------------------------------
__global__ void ctx_part_kernel(const float* __restrict__ enc) {
    int b = blockIdx.x, c = blockIdx.y;
    int tid = threadIdx.x;
    float4 a = make_float4(0.f, 0.f, 0.f, 0.f);
    int l0 = c * (L / LSPLIT);
    for (int j = 0; j < L / LSPLIT; j++) {
        int l = l0 + j;
        float w = g_attn[b * L + l];
        float4 e = ((const float4*)(enc + (size_t)l * B * H + (size_t)b * H))[tid];
        a.x += w * e.x; a.y += w * e.y; a.z += w * e.z; a.w += w * e.w;
    }
    ((float4*)(g_ctxpart + ((size_t)(b * LSPLIT + c)) * H))[tid] = a;
}

__global__ void ctx_reduce_kernel() {
    int b = blockIdx.x, tid = threadIdx.x;
    float4 s = make_float4(0.f, 0.f, 0.f, 0.f);
#pragma unroll
    for (int c = 0; c < LSPLIT; c++) {
        float4 p = ((const float4*)(g_ctxpart + ((size_t)(b * LSPLIT + c)) * H))[tid];
        s.x += p.x; s.y += p.y; s.z += p.z; s.w += p.w;
    }
    ((float4*)(g_ctx + (size_t)b * H))[tid] = s;
}

// ---------------------------------------------------------------------------
// 5) concat -> g_concat[b][i]
// ---------------------------------------------------------------------------
__global__ void concat_kernel(const float* __restrict__ cw,
                              const float* __restrict__ cb) {
    int i = blockIdx.x;
    __shared__ float sw[2 * H];
    for (int k = threadIdx.x; k < 2 * H; k += blockDim.x)
        sw[k] = cw[(size_t)i * 2 * H + k];
    __syncthreads();
    int wid = threadIdx.x >> 5, lane = threadIdx.x & 31;
#pragma unroll
    for (int t = 0; t < 8; t++) {
        int b = wid + 8 * t;
        const float* hr = g_hnew + b * H;
        const float* cr = g_ctx + b * H;
        float s = 0.f;
        for (int k = lane; k < H; k += 32)
            s += hr[k] * sw[k] + cr[k] * sw[k + H];
        s = warp_sum(s);
        if (lane == 0) g_concat[(size_t)b * H + i] = tanhf(s + cb[i]);
    }
}

// ---------------------------------------------------------------------------
// 6) logits: single-term tf32 mma.sync GEMM (minimal instruction count).
//    Block = 128V x 64B, 8 warps (4Mx2N), warp tile 32x32.
//    Smem: natural [row][k] layout, pitch 20 (conflict-free fragments).
//    KC=16 double-buffered with register prefetch. cvt.rna at store time.
// ---------------------------------------------------------------------------
__global__ __launch_bounds__(256) void logits_tf32(
        const float* __restrict__ wp, const float* __restrict__ bp,
        const float* __restrict__ wc, const float* __restrict__ bc,
        float* __restrict__ out) {
    __shared__ float Wt[2][TVL * PITCH];   // [v][k]
    __shared__ float Xt[2][B * PITCH];     // [b][k]

    int tid = threadIdx.x;
    int wid = tid >> 5, lane = tid & 31;
    int grp = lane >> 2, tig = lane & 3;
    int warpM = wid & 3, warpN = wid >> 2;

    int v0 = blockIdx.x * TVL;
    const float* W; const float* bias; float* obase;
    if (v0 < VP) { W = wp; bias = bp; obase = out; }
    else { W = wc; bias = bc; obase = out + (size_t)B * VP; v0 -= VP; }

    float acc[2][4][4];
#pragma unroll
    for (int i = 0; i < 2; i++)
#pragma unroll
        for (int j = 0; j < 4; j++)
#pragma unroll
            for (int q = 0; q < 4; q++) acc[i][j][q] = 0.f;

    // loader indices: W 2 float4/thread (f = tid + r*256: v = f>>2, kq = f&3),
    // X 1 float4/thread (b = tid>>2, kq = tid&3)
    int xb = tid >> 2, xkq = tid & 3;

    // ---- prime buffer 0 ----
    {
#pragma unroll
        for (int r = 0; r < 2; r++) {
            int f = tid + r * 256;
            int v = f >> 2, kq = f & 3;
            float4 w4 = *(const float4*)(W + (size_t)(v0 + v) * H + kq * 4);
            float4 c4 = make_float4(f2tf32f(w4.x), f2tf32f(w4.y),
                                    f2tf32f(w4.z), f2tf32f(w4.w));
            *(float4*)&Wt[0][v * PITCH + kq * 4] = c4;
        }
        float4 x4 = *(const float4*)(g_concat + (size_t)xb * H + xkq * 4);
        float4 c4 = make_float4(f2tf32f(x4.x), f2tf32f(x4.y),
                                f2tf32f(x4.z), f2tf32f(x4.w));
        *(float4*)&Xt[0][xb * PITCH + xkq * 4] = c4;
    }
    __syncthreads();

    for (int t = 0; t < NKTL; t++) {
        int cur = t & 1;
        float4 wpre[2], xpre;
        if (t + 1 < NKTL) {
            int kc = (t + 1) * KCL;
#pragma unroll
            for (int r = 0; r < 2; r++) {
                int f = tid + r * 256;
                int v = f >> 2, kq = f & 3;
                wpre[r] = *(const float4*)(W + (size_t)(v0 + v) * H + kc + kq * 4);
            }
            xpre = *(const float4*)(g_concat + (size_t)xb * H + kc + xkq * 4);
        }

        // ---- compute current tile ----
#pragma unroll
        for (int ks = 0; ks < KCL / 8; ks++) {
            int k0 = ks * 8 + tig;
            uint32_t a[2][4];
#pragma unroll
            for (int mf = 0; mf < 2; mf++) {
                int m = warpM * 32 + mf * 16 + grp;
                a[mf][0] = __float_as_uint(Wt[cur][m * PITCH + k0]);
                a[mf][1] = __float_as_uint(Wt[cur][(m + 8) * PITCH + k0]);
                a[mf][2] = __float_as_uint(Wt[cur][m * PITCH + k0 + 4]);
                a[mf][3] = __float_as_uint(Wt[cur][(m + 8) * PITCH + k0 + 4]);
            }
#pragma unroll
            for (int nf = 0; nf < 4; nf++) {
                int n = warpN * 32 + nf * 8 + grp;
                uint32_t b0 = __float_as_uint(Xt[cur][n * PITCH + k0]);
                uint32_t b1 = __float_as_uint(Xt[cur][n * PITCH + k0 + 4]);
                mma_tf32(acc[0][nf], a[0], b0, b1);
                mma_tf32(acc[1][nf], a[1], b0, b1);
            }
        }

        // ---- store prefetched tile ----
        if (t + 1 < NKTL) {
            int nxt = cur ^ 1;
#pragma unroll
            for (int r = 0; r < 2; r++) {
                int f = tid + r * 256;
                int v = f >> 2, kq = f & 3;
                float4 c4 = make_float4(f2tf32f(wpre[r].x), f2tf32f(wpre[r].y),
                                        f2tf32f(wpre[r].z), f2tf32f(wpre[r].w));
                *(float4*)&Wt[nxt][v * PITCH + kq * 4] = c4;
            }
            float4 c4 = make_float4(f2tf32f(xpre.x), f2tf32f(xpre.y),
                                    f2tf32f(xpre.z), f2tf32f(xpre.w));
            *(float4*)&Xt[nxt][xb * PITCH + xkq * 4] = c4;
        }
        __syncthreads();
    }

    // ---- epilogue (same fragment mapping as validated R5 kernel) ----
#pragma unroll
    for (int mf = 0; mf < 2; mf++) {
        int vr = v0 + warpM * 32 + mf * 16 + grp;
        float b0 = bias[vr], b1 = bias[vr + 8];
#pragma unroll
        for (int nf = 0; nf < 4; nf++) {
            int bcol = warpN * 32 + nf * 8 + 2 * tig;
            obase[(size_t)bcol * VP + vr]           = acc[mf][nf][0] + b0;
            obase[(size_t)(bcol + 1) * VP + vr]     = acc[mf][nf][1] + b0;
            obase[(size_t)bcol * VP + vr + 8]       = acc[mf][nf][2] + b1;
            obase[(size_t)(bcol + 1) * VP + vr + 8] = acc[mf][nf][3] + b1;
        }
    }
}

// ---------------------------------------------------------------------------
extern "C" void kernel_launch(void* const* d_in, const int* in_sizes, int n_in,
                              void* d_out, int out_size) {
    const int*   seq         = (const int*)d_in[0];
    const float* last_hidden = (const float*)d_in[1];
    const float* enc         = (const float*)d_in[2];
    const float* emb         = (const float*)d_in[3];
    const float* w_ih        = (const float*)d_in[4];
    const float* w_hh        = (const float*)d_in[5];
    const float* b_ih        = (const float*)d_in[6];
    const float* b_hh        = (const float*)d_in[7];
    const float* concat_w    = (const float*)d_in[8];
    const float* concat_b    = (const float*)d_in[9];
    const float* owp         = (const float*)d_in[10];
    const float* obp         = (const float*)d_in[11];
    const float* owc         = (const float*)d_in[12];
    const float* obc         = (const float*)d_in[13];

    float* out        = (float*)d_out;
    float* out_hidden = out + (size_t)B * (VP + VC);   // [1,B,H]
    float* out_attn   = out_hidden + (size_t)B * H;    // [B,1,L]

    gru_kernel<<<H, 256>>>(seq, last_hidden, emb, w_ih, w_hh, b_ih, b_hh, out_hidden);
    scores_kernel<<<L, 256>>>(enc);
    softmax_kernel<<<B, 256>>>(out_attn);
    ctx_part_kernel<<<dim3(B, LSPLIT), 256>>>(enc);
    ctx_reduce_kernel<<<B, 256>>>();
    concat_kernel<<<H, 256>>>(concat_w, concat_b);
    logits_tf32<<<(VP + VC) / TVL, 256>>>(owp, obp, owc, obc, out);
}

// round 8
// speedup vs baseline: 1.9060x; 1.2801x over previous
#include <cuda_runtime.h>
#include <math.h>
#include <stdint.h>

#define H  1024
#define B  64
#define L  1024
#define VP 32000
#define VC 32000

// ---- flash attention config ----
#define CS   8              // l-chunks per batch row
#define LPW  (L / CS / 8)   // 16 l's per warp
#define NPART 64            // partials per batch row (CS * 8 warps)

// ---- logits tf32 GEMM config ----
#define TVL   128
#define KCL   32
#define NKTL  (H / KCL)     // 32 tiles
#define PITCH 36            // conflict-free padded pitch for k-row
#define SM_LOGITS ((2 * TVL * PITCH + 2 * B * PITCH) * 4)

// ---- scratch ----
__device__ __align__(16) float g_hnew[B * H];
__device__ __align__(16) float g_scores[B * L];
__device__ __align__(16) float g_ctxpart[B * NPART * H];   // 16.7 MB
__device__ float g_pm[B * NPART];
__device__ float g_ps[B * NPART];
__device__ __align__(16) float g_ctx[B * H];
__device__ __align__(16) float g_concat[B * H];   // [b][k]

__device__ __forceinline__ float warp_sum(float v) {
#pragma unroll
    for (int o = 16; o; o >>= 1) v += __shfl_xor_sync(0xffffffffu, v, o);
    return v;
}
__device__ __forceinline__ float f2tf32f(float x) {
    uint32_t u; asm("cvt.rna.tf32.f32 %0, %1;" : "=r"(u) : "f"(x));
    return __uint_as_float(u);
}
__device__ __forceinline__ void mma_tf32(float* c, const uint32_t* a,
                                         uint32_t b0, uint32_t b1) {
    asm volatile(
        "mma.sync.aligned.m16n8k8.row.col.f32.tf32.tf32.f32 "
        "{%0,%1,%2,%3}, {%4,%5,%6,%7}, {%8,%9}, {%0,%1,%2,%3};"
        : "+f"(c[0]), "+f"(c[1]), "+f"(c[2]), "+f"(c[3])
        : "r"(a[0]), "r"(a[1]), "r"(a[2]), "r"(a[3]), "r"(b0), "r"(b1));
}

// ---------------------------------------------------------------------------
// 1) Fused GRU step (measured-good)
// ---------------------------------------------------------------------------
__global__ void gru_kernel(const int* __restrict__ seq,
                           const float* __restrict__ hprev,
                           const float* __restrict__ emb,
                           const float* __restrict__ w_ih,
                           const float* __restrict__ w_hh,
                           const float* __restrict__ b_ih,
                           const float* __restrict__ b_hh,
                           float* __restrict__ hidden_out) {
    int i = blockIdx.x;
    __shared__ float sw[6][H];
    for (int k = threadIdx.x; k < H; k += blockDim.x) {
        sw[0][k] = w_ih[(size_t)i * H + k];
        sw[1][k] = w_ih[(size_t)(i + H) * H + k];
        sw[2][k] = w_ih[(size_t)(i + 2 * H) * H + k];
        sw[3][k] = w_hh[(size_t)i * H + k];
        sw[4][k] = w_hh[(size_t)(i + H) * H + k];
        sw[5][k] = w_hh[(size_t)(i + 2 * H) * H + k];
    }
    __syncthreads();
    int wid = threadIdx.x >> 5, lane = threadIdx.x & 31;
#pragma unroll
    for (int t = 0; t < 8; t++) {
        int b = wid + 8 * t;
        const float* xr = emb + (size_t)seq[b] * H;
        const float* hr = hprev + (size_t)b * H;
        float sir = 0.f, siz = 0.f, sin_ = 0.f, shr = 0.f, shz = 0.f, shn = 0.f;
        for (int k = lane; k < H; k += 32) {
            float xv = xr[k], hv = hr[k];
            sir += xv * sw[0][k]; siz += xv * sw[1][k]; sin_ += xv * sw[2][k];
            shr += hv * sw[3][k]; shz += hv * sw[4][k]; shn += hv * sw[5][k];
        }
        sir = warp_sum(sir); siz = warp_sum(siz); sin_ = warp_sum(sin_);
        shr = warp_sum(shr); shz = warp_sum(shz); shn = warp_sum(shn);
        if (lane == 0) {
            float gr = sir + b_ih[i] + shr + b_hh[i];
            float gz = siz + b_ih[i + H] + shz + b_hh[i + H];
            float r = 1.f / (1.f + expf(-gr));
            float z = 1.f / (1.f + expf(-gz));
            float n = tanhf(sin_ + b_ih[i + 2 * H] + r * (shn + b_hh[i + 2 * H]));
            float hv = hprev[(size_t)b * H + i];
            float hn = (1.f - z) * n + z * hv;
            g_hnew[b * H + i] = hn;
            hidden_out[b * H + i] = hn;
        }
    }
}

// ---------------------------------------------------------------------------
// 2) Single-pass warp-flash attention: scores + online softmax + context
//    partials, ONE read of enc, no block-level syncs in the hot loop.
//    Grid (B, CS); each warp owns LPW consecutive l's of one batch row.
// ---------------------------------------------------------------------------
__global__ __launch_bounds__(256) void flash2_kernel(const float* __restrict__ enc) {
    int b = blockIdx.x, ch = blockIdx.y;
    int w = threadIdx.x >> 5, lane = threadIdx.x & 31;
    int l0 = ch * (L / CS) + w * LPW;

    // h_new fragment for this lane (8 float4 spanning H)
    const float4* hb = (const float4*)(g_hnew + (size_t)b * H);
    float4 h[8];
#pragma unroll
    for (int q = 0; q < 8; q++) h[q] = hb[lane + q * 32];

    float4 acc[8];
#pragma unroll
    for (int q = 0; q < 8; q++) acc[q] = make_float4(0.f, 0.f, 0.f, 0.f);
    float m = -1e30f, ssum = 0.f;

    for (int j = 0; j < LPW; j++) {
        int l = l0 + j;
        const float4* er = (const float4*)(enc + ((size_t)l * B + b) * H);
        float4 e[8];
        float d = 0.f;
#pragma unroll
        for (int q = 0; q < 8; q++) {
            e[q] = er[lane + q * 32];
            d += e[q].x * h[q].x + e[q].y * h[q].y + e[q].z * h[q].z + e[q].w * h[q].w;
        }
        d = warp_sum(d);
        if (lane == 0) g_scores[b * L + l] = d;
        float nm = fmaxf(m, d);
        float sc = expf(m - nm);
        float p = expf(d - nm);
        ssum = ssum * sc + p;
#pragma unroll
        for (int q = 0; q < 8; q++) {
            acc[q].x = acc[q].x * sc + p * e[q].x;
            acc[q].y = acc[q].y * sc + p * e[q].y;
            acc[q].z = acc[q].z * sc + p * e[q].z;
            acc[q].w = acc[q].w * sc + p * e[q].w;
        }
        m = nm;
    }

    int pidx = b * NPART + ch * 8 + w;
    float4* pp = (float4*)(g_ctxpart + (size_t)pidx * H);
#pragma unroll
    for (int q = 0; q < 8; q++) pp[lane + q * 32] = acc[q];
    if (lane == 0) { g_pm[pidx] = m; g_ps[pidx] = ssum; }
}

// ---------------------------------------------------------------------------
// 3) combine flash partials -> g_ctx
// ---------------------------------------------------------------------------
__global__ void ctx_combine2_kernel() {
    int b = blockIdx.x, tid = threadIdx.x;   // 256 threads, one float4 each
    __shared__ float sm[NPART], sw[NPART];
    if (tid < NPART) sm[tid] = g_pm[b * NPART + tid];
    __syncthreads();
    float gm = -1e30f;
#pragma unroll 8
    for (int c = 0; c < NPART; c++) gm = fmaxf(gm, sm[c]);
    if (tid < NPART) sw[tid] = expf(sm[tid] - gm);
    __syncthreads();
    float S = 0.f;
#pragma unroll 8
    for (int c = 0; c < NPART; c++) S += g_ps[b * NPART + c] * sw[c];
    float inv = 1.f / S;
    float4 a = make_float4(0.f, 0.f, 0.f, 0.f);
    for (int c = 0; c < NPART; c++) {
        float wgt = sw[c];
        float4 p = ((const float4*)(g_ctxpart + ((size_t)(b * NPART + c)) * H))[tid];
        a.x += wgt * p.x; a.y += wgt * p.y; a.z += wgt * p.z; a.w += wgt * p.w;
    }
    a.x *= inv; a.y *= inv; a.z *= inv; a.w *= inv;
    ((float4*)(g_ctx + (size_t)b * H))[tid] = a;
}

// ---------------------------------------------------------------------------
// 4) concat -> g_concat[b][i]   (4th launch: gets profiled)
// ---------------------------------------------------------------------------
__global__ void concat_kernel(const float* __restrict__ cw,
                              const float* __restrict__ cb) {
    int i = blockIdx.x;
    __shared__ float sw[2 * H];
    for (int k = threadIdx.x; k < 2 * H; k += blockDim.x)
        sw[k] = cw[(size_t)i * 2 * H + k];
    __syncthreads();
    int wid = threadIdx.x >> 5, lane = threadIdx.x & 31;
#pragma unroll
    for (int t = 0; t < 8; t++) {
        int b = wid + 8 * t;
        const float* hr = g_hnew + b * H;
        const float* cr = g_ctx + b * H;
        float s = 0.f;
        for (int k = lane; k < H; k += 32)
            s += hr[k] * sw[k] + cr[k] * sw[k + H];
        s = warp_sum(s);
        if (lane == 0) g_concat[(size_t)b * H + i] = tanhf(s + cb[i]);
    }
}

// ---------------------------------------------------------------------------
// 5) logits: single-term tf32 mma.sync GEMM, KCL=32 tiles (halved cadence)
// ---------------------------------------------------------------------------
__global__ __launch_bounds__(256) void logits_tf32(
        const float* __restrict__ wp, const float* __restrict__ bp,
        const float* __restrict__ wc, const float* __restrict__ bc,
        float* __restrict__ out) {
    extern __shared__ float smf[];
    float* Wt = smf;                        // [2][TVL * PITCH]
    float* Xt = smf + 2 * TVL * PITCH;      // [2][B * PITCH]

    int tid = threadIdx.x;
    int wid = tid >> 5, lane = tid & 31;
    int grp = lane >> 2, tig = lane & 3;
    int warpM = wid & 3, warpN = wid >> 2;

    int v0 = blockIdx.x * TVL;
    const float* W; const float* bias; float* obase;
    if (v0 < VP) { W = wp; bias = bp; obase = out; }
    else { W = wc; bias = bc; obase = out + (size_t)B * VP; v0 -= VP; }

    float acc[2][4][4];
#pragma unroll
    for (int i = 0; i < 2; i++)
#pragma unroll
        for (int j = 0; j < 4; j++)
#pragma unroll
            for (int q = 0; q < 4; q++) acc[i][j][q] = 0.f;

    // loader: W 4 float4/thread (f = tid + r*256: v = f>>3, kq = f&7)
    //         X 2 float4/thread (f = tid + r*256: b = f>>3, kq = f&7)
    // ---- prime buffer 0 ----
    {
#pragma unroll
        for (int r = 0; r < 4; r++) {
            int f = tid + r * 256;
            int v = f >> 3, kq = f & 7;
            float4 w4 = *(const float4*)(W + (size_t)(v0 + v) * H + kq * 4);
            float4 c4 = make_float4(f2tf32f(w4.x), f2tf32f(w4.y),
                                    f2tf32f(w4.z), f2tf32f(w4.w));
            *(float4*)&Wt[v * PITCH + kq * 4] = c4;
        }
#pragma unroll
        for (int r = 0; r < 2; r++) {
            int f = tid + r * 256;
            int xb = f >> 3, kq = f & 7;
            float4 x4 = *(const float4*)(g_concat + (size_t)xb * H + kq * 4);
            float4 c4 = make_float4(f2tf32f(x4.x), f2tf32f(x4.y),
                                    f2tf32f(x4.z), f2tf32f(x4.w));
            *(float4*)&Xt[xb * PITCH + kq * 4] = c4;
        }
    }
    __syncthreads();

    for (int t = 0; t < NKTL; t++) {
        int cur = t & 1;
        float* Wc = Wt + cur * TVL * PITCH;
        float* Xc = Xt + cur * B * PITCH;
        float4 wpre[4], xpre[2];
        if (t + 1 < NKTL) {
            int kc = (t + 1) * KCL;
#pragma unroll
            for (int r = 0; r < 4; r++) {
                int f = tid + r * 256;
                int v = f >> 3, kq = f & 7;
                wpre[r] = *(const float4*)(W + (size_t)(v0 + v) * H + kc + kq * 4);
            }
#pragma unroll
            for (int r = 0; r < 2; r++) {
                int f = tid + r * 256;
                int xb = f >> 3, kq = f & 7;
                xpre[r] = *(const float4*)(g_concat + (size_t)xb * H + kc + kq * 4);
            }
        }

        // ---- compute current tile ----
#pragma unroll
        for (int ks = 0; ks < KCL / 8; ks++) {
            int k0 = ks * 8 + tig;
            uint32_t a[2][4];
#pragma unroll
            for (int mf = 0; mf < 2; mf++) {
                int mm = warpM * 32 + mf * 16 + grp;
                a[mf][0] = __float_as_uint(Wc[mm * PITCH + k0]);
                a[mf][1] = __float_as_uint(Wc[(mm + 8) * PITCH + k0]);
                a[mf][2] = __float_as_uint(Wc[mm * PITCH + k0 + 4]);
                a[mf][3] = __float_as_uint(Wc[(mm + 8) * PITCH + k0 + 4]);
            }
#pragma unroll
            for (int nf = 0; nf < 4; nf++) {
                int n = warpN * 32 + nf * 8 + grp;
                uint32_t b0 = __float_as_uint(Xc[n * PITCH + k0]);
                uint32_t b1 = __float_as_uint(Xc[n * PITCH + k0 + 4]);
                mma_tf32(acc[0][nf], a[0], b0, b1);
                mma_tf32(acc[1][nf], a[1], b0, b1);
            }
        }

        // ---- store prefetched tile ----
        if (t + 1 < NKTL) {
            float* Wn = Wt + (cur ^ 1) * TVL * PITCH;
            float* Xn = Xt + (cur ^ 1) * B * PITCH;
#pragma unroll
            for (int r = 0; r < 4; r++) {
                int f = tid + r * 256;
                int v = f >> 3, kq = f & 7;
                float4 c4 = make_float4(f2tf32f(wpre[r].x), f2tf32f(wpre[r].y),
                                        f2tf32f(wpre[r].z), f2tf32f(wpre[r].w));
                *(float4*)&Wn[v * PITCH + kq * 4] = c4;
            }
#pragma unroll
            for (int r = 0; r < 2; r++) {
                int f = tid + r * 256;
                int xb = f >> 3, kq = f & 7;
                float4 c4 = make_float4(f2tf32f(xpre[r].x), f2tf32f(xpre[r].y),
                                        f2tf32f(xpre[r].z), f2tf32f(xpre[r].w));
                *(float4*)&Xn[xb * PITCH + kq * 4] = c4;
            }
        }
        __syncthreads();
    }

    // ---- epilogue (fragment mapping validated in R5/R7) ----
#pragma unroll
    for (int mf = 0; mf < 2; mf++) {
        int vr = v0 + warpM * 32 + mf * 16 + grp;
        float b0 = bias[vr], b1 = bias[vr + 8];
#pragma unroll
        for (int nf = 0; nf < 4; nf++) {
            int bcol = warpN * 32 + nf * 8 + 2 * tig;
            obase[(size_t)bcol * VP + vr]           = acc[mf][nf][0] + b0;
            obase[(size_t)(bcol + 1) * VP + vr]     = acc[mf][nf][1] + b0;
            obase[(size_t)bcol * VP + vr + 8]       = acc[mf][nf][2] + b1;
            obase[(size_t)(bcol + 1) * VP + vr + 8] = acc[mf][nf][3] + b1;
        }
    }
}

// ---------------------------------------------------------------------------
// 6) attn-weights output softmax (from stored raw scores)
// ---------------------------------------------------------------------------
__global__ void softmax_out_kernel(float* __restrict__ attn_out) {
    int b = blockIdx.x, tid = threadIdx.x;
    __shared__ float sh[8];
    __shared__ float sval;
    float m = -1e30f;
    for (int l = tid; l < L; l += 256) m = fmaxf(m, g_scores[b * L + l]);
#pragma unroll
    for (int o = 16; o; o >>= 1) m = fmaxf(m, __shfl_xor_sync(0xffffffffu, m, o));
    if ((tid & 31) == 0) sh[tid >> 5] = m;
    __syncthreads();
    if (tid == 0) {
        float mm = sh[0];
        for (int j = 1; j < 8; j++) mm = fmaxf(mm, sh[j]);
        sval = mm;
    }
    __syncthreads();
    m = sval;
    float s = 0.f;
    for (int l = tid; l < L; l += 256) s += expf(g_scores[b * L + l] - m);
    s = warp_sum(s);
    __syncthreads();
    if ((tid & 31) == 0) sh[tid >> 5] = s;
    __syncthreads();
    if (tid == 0) {
        float ss = 0.f;
        for (int j = 0; j < 8; j++) ss += sh[j];
        sval = ss;
    }
    __syncthreads();
    float inv = 1.f / sval;
    for (int l = tid; l < L; l += 256)
        attn_out[b * L + l] = expf(g_scores[b * L + l] - m) * inv;
}

// ---------------------------------------------------------------------------
extern "C" void kernel_launch(void* const* d_in, const int* in_sizes, int n_in,
                              void* d_out, int out_size) {
    const int*   seq         = (const int*)d_in[0];
    const float* last_hidden = (const float*)d_in[1];
    const float* enc         = (const float*)d_in[2];
    const float* emb         = (const float*)d_in[3];
    const float* w_ih        = (const float*)d_in[4];
    const float* w_hh        = (const float*)d_in[5];
    const float* b_ih        = (const float*)d_in[6];
    const float* b_hh        = (const float*)d_in[7];
    const float* concat_w    = (const float*)d_in[8];
    const float* concat_b    = (const float*)d_in[9];
    const float* owp         = (const float*)d_in[10];
    const float* obp         = (const float*)d_in[11];
    const float* owc         = (const float*)d_in[12];
    const float* obc         = (const float*)d_in[13];

    float* out        = (float*)d_out;
    float* out_hidden = out + (size_t)B * (VP + VC);   // [1,B,H]
    float* out_attn   = out_hidden + (size_t)B * H;    // [B,1,L]

    cudaFuncSetAttribute(logits_tf32, cudaFuncAttributeMaxDynamicSharedMemorySize, SM_LOGITS);

    gru_kernel<<<H, 256>>>(seq, last_hidden, emb, w_ih, w_hh, b_ih, b_hh, out_hidden);
    flash2_kernel<<<dim3(B, CS), 256>>>(enc);
    ctx_combine2_kernel<<<B, 256>>>();
    concat_kernel<<<H, 256>>>(concat_w, concat_b);          // 4th: profiled
    logits_tf32<<<(VP + VC) / TVL, 256, SM_LOGITS>>>(owp, obp, owc, obc, out);
    softmax_out_kernel<<<B, 256>>>(out_attn);
}

// round 9
// speedup vs baseline: 2.7897x; 1.4636x over previous
#include <cuda_runtime.h>
#include <math.h>
#include <stdint.h>

#define H  1024
#define B  64
#define L  1024
#define VP 32000
#define VC 32000

// ---- flash attention config ----
#define CS   8
#define LPW  (L / CS / 8)
#define NPART 64

// ---- tf32 GEMM config (generic + logits) ----
#define TVL   128
#define KCL   32
#define PITCH 36
#define SM_GEMM ((2 * TVL * PITCH + 2 * B * PITCH) * 4)

#define GRU_ROWS   6144      // 3H w_ih + 3H w_hh
#define GRU_SPLITS 2
#define CAT_ROWS   1024
#define CAT_SPLITS 4

// ---- scratch ----
__device__ __align__(16) float g_xh[2 * B * H];                 // x | h_prev, [b][k]
__device__ __align__(16) float g_gatep[GRU_SPLITS * GRU_ROWS * B];
__device__ __align__(16) float g_hnew[B * H];
__device__ __align__(16) float g_hc[B * 2 * H];                 // [b][ h_new | ctx ]
__device__ __align__(16) float g_scores[B * L];
__device__ __align__(16) float g_ctxpart[B * NPART * H];
__device__ float g_pm[B * NPART];
__device__ float g_ps[B * NPART];
__device__ __align__(16) float g_cpart[CAT_SPLITS * CAT_ROWS * B];
__device__ __align__(16) float g_concat[B * H];                 // [b][k]

__device__ __forceinline__ float warp_sum(float v) {
#pragma unroll
    for (int o = 16; o; o >>= 1) v += __shfl_xor_sync(0xffffffffu, v, o);
    return v;
}
__device__ __forceinline__ float f2tf32f(float x) {
    uint32_t u; asm("cvt.rna.tf32.f32 %0, %1;" : "=r"(u) : "f"(x));
    return __uint_as_float(u);
}
__device__ __forceinline__ void mma_tf32(float* c, const uint32_t* a,
                                         uint32_t b0, uint32_t b1) {
    asm volatile(
        "mma.sync.aligned.m16n8k8.row.col.f32.tf32.tf32.f32 "
        "{%0,%1,%2,%3}, {%4,%5,%6,%7}, {%8,%9}, {%0,%1,%2,%3};"
        : "+f"(c[0]), "+f"(c[1]), "+f"(c[2]), "+f"(c[3])
        : "r"(a[0]), "r"(a[1]), "r"(a[2]), "r"(a[3]), "r"(b0), "r"(b1));
}

// ---------------------------------------------------------------------------
// 0) pack x (embedding gather) and h_prev -> g_xh
// ---------------------------------------------------------------------------
__global__ void pack_xh_kernel(const int* __restrict__ seq,
                               const float* __restrict__ hprev,
                               const float* __restrict__ emb) {
    int b = blockIdx.x, tid = threadIdx.x;
    ((float4*)(g_xh + (size_t)b * H))[tid] =
        ((const float4*)(emb + (size_t)seq[b] * H))[tid];
    ((float4*)(g_xh + (size_t)(B + b) * H))[tid] =
        ((const float4*)(hprev + (size_t)b * H))[tid];
}

// ---------------------------------------------------------------------------
// Generic single-tf32 MMA GEMM, split-K, raw-partial epilogue.
// Block = 128 rows x 64 batch, 8 warps (4Mx2N), KCL=32 double-buffered.
// blocks [0, halfBlocks): A0/X0 rows; rest: A1/X1 (rows rebased).
// out[(split*totalRows + row)*B + b] = partial sum over this K-split.
// ---------------------------------------------------------------------------
__global__ __launch_bounds__(256) void gemm_part(
        const float* __restrict__ A0, const float* __restrict__ A1,
        const float* __restrict__ X0, const float* __restrict__ X1,
        float* __restrict__ outp, int ldA, int kPerSplit, int halfBlocks,
        int totalRows) {
    extern __shared__ float smf[];
    float* Wt = smf;
    float* Xt = smf + 2 * TVL * PITCH;

    int tid = threadIdx.x;
    int wid = tid >> 5, lane = tid & 31;
    int grp = lane >> 2, tig = lane & 3;
    int warpM = wid & 3, warpN = wid >> 2;

    const float* A = A0; const float* X = X0;
    int blk = blockIdx.x;
    int outRowBase = blk * TVL;
    if (halfBlocks > 0 && blk >= halfBlocks) { A = A1; X = X1; blk -= halfBlocks; }
    int a0 = blk * TVL;
    int kOff = blockIdx.y * kPerSplit;
    int nt = kPerSplit / KCL;

    float acc[2][4][4];
#pragma unroll
    for (int i = 0; i < 2; i++)
#pragma unroll
        for (int j = 0; j < 4; j++)
#pragma unroll
            for (int q = 0; q < 4; q++) acc[i][j][q] = 0.f;

    // ---- prime buffer 0 ----
#pragma unroll
    for (int r = 0; r < 4; r++) {
        int f = tid + r * 256;
        int v = f >> 3, kq = f & 7;
        float4 w4 = *(const float4*)(A + (size_t)(a0 + v) * ldA + kOff + kq * 4);
        *(float4*)&Wt[v * PITCH + kq * 4] =
            make_float4(f2tf32f(w4.x), f2tf32f(w4.y), f2tf32f(w4.z), f2tf32f(w4.w));
    }
#pragma unroll
    for (int r = 0; r < 2; r++) {
        int f = tid + r * 256;
        int xb = f >> 3, kq = f & 7;
        float4 x4 = *(const float4*)(X + (size_t)xb * ldA + kOff + kq * 4);
        *(float4*)&Xt[xb * PITCH + kq * 4] =
            make_float4(f2tf32f(x4.x), f2tf32f(x4.y), f2tf32f(x4.z), f2tf32f(x4.w));
    }
    __syncthreads();

    for (int t = 0; t < nt; t++) {
        int cur = t & 1;
        float* Wc = Wt + cur * TVL * PITCH;
        float* Xc = Xt + cur * B * PITCH;
        float4 wpre[4], xpre[2];
        if (t + 1 < nt) {
            int kc = kOff + (t + 1) * KCL;
#pragma unroll
            for (int r = 0; r < 4; r++) {
                int f = tid + r * 256;
                int v = f >> 3, kq = f & 7;
                wpre[r] = *(const float4*)(A + (size_t)(a0 + v) * ldA + kc + kq * 4);
            }
#pragma unroll
            for (int r = 0; r < 2; r++) {
                int f = tid + r * 256;
                int xb = f >> 3, kq = f & 7;
                xpre[r] = *(const float4*)(X + (size_t)xb * ldA + kc + kq * 4);
            }
        }
#pragma unroll
        for (int ks = 0; ks < KCL / 8; ks++) {
            int k0 = ks * 8 + tig;
            uint32_t a[2][4];
#pragma unroll
            for (int mf = 0; mf < 2; mf++) {
                int mm = warpM * 32 + mf * 16 + grp;
                a[mf][0] = __float_as_uint(Wc[mm * PITCH + k0]);
                a[mf][1] = __float_as_uint(Wc[(mm + 8) * PITCH + k0]);
                a[mf][2] = __float_as_uint(Wc[mm * PITCH + k0 + 4]);
                a[mf][3] = __float_as_uint(Wc[(mm + 8) * PITCH + k0 + 4]);
            }
#pragma unroll
            for (int nf = 0; nf < 4; nf++) {
                int n = warpN * 32 + nf * 8 + grp;
                uint32_t b0 = __float_as_uint(Xc[n * PITCH + k0]);
                uint32_t b1 = __float_as_uint(Xc[n * PITCH + k0 + 4]);
                mma_tf32(acc[0][nf], a[0], b0, b1);
                mma_tf32(acc[1][nf], a[1], b0, b1);
            }
        }
        if (t + 1 < nt) {
            float* Wn = Wt + (cur ^ 1) * TVL * PITCH;
            float* Xn = Xt + (cur ^ 1) * B * PITCH;
#pragma unroll
            for (int r = 0; r < 4; r++) {
                int f = tid + r * 256;
                int v = f >> 3, kq = f & 7;
                *(float4*)&Wn[v * PITCH + kq * 4] =
                    make_float4(f2tf32f(wpre[r].x), f2tf32f(wpre[r].y),
                                f2tf32f(wpre[r].z), f2tf32f(wpre[r].w));
            }
#pragma unroll
            for (int r = 0; r < 2; r++) {
                int f = tid + r * 256;
                int xb = f >> 3, kq = f & 7;
                *(float4*)&Xn[xb * PITCH + kq * 4] =
                    make_float4(f2tf32f(xpre[r].x), f2tf32f(xpre[r].y),
                                f2tf32f(xpre[r].z), f2tf32f(xpre[r].w));
            }
        }
        __syncthreads();
    }

    float* o = outp + (size_t)blockIdx.y * totalRows * B;
#pragma unroll
    for (int mf = 0; mf < 2; mf++) {
        int vr = outRowBase + warpM * 32 + mf * 16 + grp;
#pragma unroll
        for (int nf = 0; nf < 4; nf++) {
            int bcol = warpN * 32 + nf * 8 + 2 * tig;
            o[(size_t)vr * B + bcol]           = acc[0 * 2 + mf][nf][0];
            o[(size_t)vr * B + bcol + 1]       = acc[mf][nf][1];
            o[(size_t)(vr + 8) * B + bcol]     = acc[mf][nf][2];
            o[(size_t)(vr + 8) * B + bcol + 1] = acc[mf][nf][3];
        }
    }
}

// ---------------------------------------------------------------------------
// gate combine: sum split partials, apply GRU nonlinearity -> h_new
// ---------------------------------------------------------------------------
__global__ void gru_gate_kernel(const float* __restrict__ hprev,
                                const float* __restrict__ b_ih,
                                const float* __restrict__ b_hh,
                                float* __restrict__ hidden_out) {
    int tid = threadIdx.x;
    int b = tid & 63;
    int i = blockIdx.x * 4 + (tid >> 6);
#define GP(row) (g_gatep[(size_t)(row) * B + b] + \
                 g_gatep[(size_t)(GRU_ROWS + (row)) * B + b])
    float gir = GP(i),          giz = GP(H + i),      gin = GP(2 * H + i);
    float ghr = GP(3 * H + i),  ghz = GP(4 * H + i),  ghn = GP(5 * H + i);
#undef GP
    float r = 1.f / (1.f + expf(-(gir + b_ih[i] + ghr + b_hh[i])));
    float z = 1.f / (1.f + expf(-(giz + b_ih[H + i] + ghz + b_hh[H + i])));
    float n = tanhf(gin + b_ih[2 * H + i] + r * (ghn + b_hh[2 * H + i]));
    float hv = hprev[(size_t)b * H + i];
    float hn = (1.f - z) * n + z * hv;
    g_hnew[(size_t)b * H + i] = hn;
    g_hc[(size_t)b * 2 * H + i] = hn;
    hidden_out[(size_t)b * H + i] = hn;
}

// ---------------------------------------------------------------------------
// flash attention (R8 measured-good)
// ---------------------------------------------------------------------------
__global__ __launch_bounds__(256) void flash2_kernel(const float* __restrict__ enc) {
    int b = blockIdx.x, ch = blockIdx.y;
    int w = threadIdx.x >> 5, lane = threadIdx.x & 31;
    int l0 = ch * (L / CS) + w * LPW;

    const float4* hb = (const float4*)(g_hnew + (size_t)b * H);
    float4 h[8];
#pragma unroll
    for (int q = 0; q < 8; q++) h[q] = hb[lane + q * 32];

    float4 acc[8];
#pragma unroll
    for (int q = 0; q < 8; q++) acc[q] = make_float4(0.f, 0.f, 0.f, 0.f);
    float m = -1e30f, ssum = 0.f;

    for (int j = 0; j < LPW; j++) {
        int l = l0 + j;
        const float4* er = (const float4*)(enc + ((size_t)l * B + b) * H);
        float4 e[8];
        float d = 0.f;
#pragma unroll
        for (int q = 0; q < 8; q++) {
            e[q] = er[lane + q * 32];
            d += e[q].x * h[q].x + e[q].y * h[q].y + e[q].z * h[q].z + e[q].w * h[q].w;
        }
        d = warp_sum(d);
        if (lane == 0) g_scores[b * L + l] = d;
        float nm = fmaxf(m, d);
        float sc = expf(m - nm);
        float p = expf(d - nm);
        ssum = ssum * sc + p;
#pragma unroll
        for (int q = 0; q < 8; q++) {
            acc[q].x = acc[q].x * sc + p * e[q].x;
            acc[q].y = acc[q].y * sc + p * e[q].y;
            acc[q].z = acc[q].z * sc + p * e[q].z;
            acc[q].w = acc[q].w * sc + p * e[q].w;
        }
        m = nm;
    }

    int pidx = b * NPART + ch * 8 + w;
    float4* pp = (float4*)(g_ctxpart + (size_t)pidx * H);
#pragma unroll
    for (int q = 0; q < 8; q++) pp[lane + q * 32] = acc[q];
    if (lane == 0) { g_pm[pidx] = m; g_ps[pidx] = ssum; }
}

__global__ void ctx_combine2_kernel() {
    int b = blockIdx.x, tid = threadIdx.x;
    __shared__ float sm[NPART], sw[NPART];
    if (tid < NPART) sm[tid] = g_pm[b * NPART + tid];
    __syncthreads();
    float gm = -1e30f;
#pragma unroll 8
    for (int c = 0; c < NPART; c++) gm = fmaxf(gm, sm[c]);
    if (tid < NPART) sw[tid] = expf(sm[tid] - gm);
    __syncthreads();
    float S = 0.f;
#pragma unroll 8
    for (int c = 0; c < NPART; c++) S += g_ps[b * NPART + c] * sw[c];
    float inv = 1.f / S;
    float4 a = make_float4(0.f, 0.f, 0.f, 0.f);
    for (int c = 0; c < NPART; c++) {
        float wgt = sw[c];
        float4 p = ((const float4*)(g_ctxpart + ((size_t)(b * NPART + c)) * H))[tid];
        a.x += wgt * p.x; a.y += wgt * p.y; a.z += wgt * p.z; a.w += wgt * p.w;
    }
    a.x *= inv; a.y *= inv; a.z *= inv; a.w *= inv;
    ((float4*)(g_hc + (size_t)b * 2 * H + H))[tid] = a;
}

// ---------------------------------------------------------------------------
// concat reduce + tanh -> g_concat[b][i]
// ---------------------------------------------------------------------------
__global__ void cat_reduce_kernel(const float* __restrict__ cb) {
    int tid = threadIdx.x;
    int b = tid & 63;
    int i = blockIdx.x * 4 + (tid >> 6);
    float s = 0.f;
#pragma unroll
    for (int y = 0; y < CAT_SPLITS; y++)
        s += g_cpart[(size_t)(y * CAT_ROWS + i) * B + b];
    g_concat[(size_t)b * H + i] = tanhf(s + cb[i]);
}

// ---------------------------------------------------------------------------
// logits: single-tf32 GEMM, KCL=32 (R8 version, measured-good)
// ---------------------------------------------------------------------------
__global__ __launch_bounds__(256) void logits_tf32(
        const float* __restrict__ wp, const float* __restrict__ bp,
        const float* __restrict__ wc, const float* __restrict__ bc,
        float* __restrict__ out) {
    extern __shared__ float smf[];
    float* Wt = smf;
    float* Xt = smf + 2 * TVL * PITCH;

    int tid = threadIdx.x;
    int wid = tid >> 5, lane = tid & 31;
    int grp = lane >> 2, tig = lane & 3;
    int warpM = wid & 3, warpN = wid >> 2;

    int v0 = blockIdx.x * TVL;
    const float* W; const float* bias; float* obase;
    if (v0 < VP) { W = wp; bias = bp; obase = out; }
    else { W = wc; bias = bc; obase = out + (size_t)B * VP; v0 -= VP; }

    float acc[2][4][4];
#pragma unroll
    for (int i = 0; i < 2; i++)
#pragma unroll
        for (int j = 0; j < 4; j++)
#pragma unroll
            for (int q = 0; q < 4; q++) acc[i][j][q] = 0.f;

#pragma unroll
    for (int r = 0; r < 4; r++) {
        int f = tid + r * 256;
        int v = f >> 3, kq = f & 7;
        float4 w4 = *(const float4*)(W + (size_t)(v0 + v) * H + kq * 4);
        *(float4*)&Wt[v * PITCH + kq * 4] =
            make_float4(f2tf32f(w4.x), f2tf32f(w4.y), f2tf32f(w4.z), f2tf32f(w4.w));
    }
#pragma unroll
    for (int r = 0; r < 2; r++) {
        int f = tid + r * 256;
        int xb = f >> 3, kq = f & 7;
        float4 x4 = *(const float4*)(g_concat + (size_t)xb * H + kq * 4);
        *(float4*)&Xt[xb * PITCH + kq * 4] =
            make_float4(f2tf32f(x4.x), f2tf32f(x4.y), f2tf32f(x4.z), f2tf32f(x4.w));
    }
    __syncthreads();

    const int NT = H / KCL;
    for (int t = 0; t < NT; t++) {
        int cur = t & 1;
        float* Wc = Wt + cur * TVL * PITCH;
        float* Xc = Xt + cur * B * PITCH;
        float4 wpre[4], xpre[2];
        if (t + 1 < NT) {
            int kc = (t + 1) * KCL;
#pragma unroll
            for (int r = 0; r < 4; r++) {
                int f = tid + r * 256;
                int v = f >> 3, kq = f & 7;
                wpre[r] = *(const float4*)(W + (size_t)(v0 + v) * H + kc + kq * 4);
            }
#pragma unroll
            for (int r = 0; r < 2; r++) {
                int f = tid + r * 256;
                int xb = f >> 3, kq = f & 7;
                xpre[r] = *(const float4*)(g_concat + (size_t)xb * H + kc + kq * 4);
            }
        }
#pragma unroll
        for (int ks = 0; ks < KCL / 8; ks++) {
            int k0 = ks * 8 + tig;
            uint32_t a[2][4];
#pragma unroll
            for (int mf = 0; mf < 2; mf++) {
                int mm = warpM * 32 + mf * 16 + grp;
                a[mf][0] = __float_as_uint(Wc[mm * PITCH + k0]);
                a[mf][1] = __float_as_uint(Wc[(mm + 8) * PITCH + k0]);
                a[mf][2] = __float_as_uint(Wc[mm * PITCH + k0 + 4]);
                a[mf][3] = __float_as_uint(Wc[(mm + 8) * PITCH + k0 + 4]);
            }
#pragma unroll
            for (int nf = 0; nf < 4; nf++) {
                int n = warpN * 32 + nf * 8 + grp;
                uint32_t b0 = __float_as_uint(Xc[n * PITCH + k0]);
                uint32_t b1 = __float_as_uint(Xc[n * PITCH + k0 + 4]);
                mma_tf32(acc[0][nf], a[0], b0, b1);
                mma_tf32(acc[1][nf], a[1], b0, b1);
            }
        }
        if (t + 1 < NT) {
            float* Wn = Wt + (cur ^ 1) * TVL * PITCH;
            float* Xn = Xt + (cur ^ 1) * B * PITCH;
#pragma unroll
            for (int r = 0; r < 4; r++) {
                int f = tid + r * 256;
                int v = f >> 3, kq = f & 7;
                *(float4*)&Wn[v * PITCH + kq * 4] =
                    make_float4(f2tf32f(wpre[r].x), f2tf32f(wpre[r].y),
                                f2tf32f(wpre[r].z), f2tf32f(wpre[r].w));
            }
#pragma unroll
            for (int r = 0; r < 2; r++) {
                int f = tid + r * 256;
                int xb = f >> 3, kq = f & 7;
                *(float4*)&Xn[xb * PITCH + kq * 4] =
                    make_float4(f2tf32f(xpre[r].x), f2tf32f(xpre[r].y),
                                f2tf32f(xpre[r].z), f2tf32f(xpre[r].w));
            }
        }
        __syncthreads();
    }

#pragma unroll
    for (int mf = 0; mf < 2; mf++) {
        int vr = v0 + warpM * 32 + mf * 16 + grp;
        float b0 = bias[vr], b1 = bias[vr + 8];
#pragma unroll
        for (int nf = 0; nf < 4; nf++) {
            int bcol = warpN * 32 + nf * 8 + 2 * tig;
            obase[(size_t)bcol * VP + vr]           = acc[mf][nf][0] + b0;
            obase[(size_t)(bcol + 1) * VP + vr]     = acc[mf][nf][1] + b0;
            obase[(size_t)bcol * VP + vr + 8]       = acc[mf][nf][2] + b1;
            obase[(size_t)(bcol + 1) * VP + vr + 8] = acc[mf][nf][3] + b1;
        }
    }
}

// ---------------------------------------------------------------------------
// attn-weights output softmax
// ---------------------------------------------------------------------------
__global__ void softmax_out_kernel(float* __restrict__ attn_out) {
    int b = blockIdx.x, tid = threadIdx.x;
    __shared__ float sh[8];
    __shared__ float sval;
    float m = -1e30f;
    for (int l = tid; l < L; l += 256) m = fmaxf(m, g_scores[b * L + l]);
#pragma unroll
    for (int o = 16; o; o >>= 1) m = fmaxf(m, __shfl_xor_sync(0xffffffffu, m, o));
    if ((tid & 31) == 0) sh[tid >> 5] = m;
    __syncthreads();
    if (tid == 0) {
        float mm = sh[0];
        for (int j = 1; j < 8; j++) mm = fmaxf(mm, sh[j]);
        sval = mm;
    }
    __syncthreads();
    m = sval;
    float s = 0.f;
    for (int l = tid; l < L; l += 256) s += expf(g_scores[b * L + l] - m);
    s = warp_sum(s);
    __syncthreads();
    if ((tid & 31) == 0) sh[tid >> 5] = s;
    __syncthreads();
    if (tid == 0) {
        float ss = 0.f;
        for (int j = 0; j < 8; j++) ss += sh[j];
        sval = ss;
    }
    __syncthreads();
    float inv = 1.f / sval;
    for (int l = tid; l < L; l += 256)
        attn_out[b * L + l] = expf(g_scores[b * L + l] - m) * inv;
}

// ---------------------------------------------------------------------------
extern "C" void kernel_launch(void* const* d_in, const int* in_sizes, int n_in,
                              void* d_out, int out_size) {
    const int*   seq         = (const int*)d_in[0];
    const float* last_hidden = (const float*)d_in[1];
    const float* enc         = (const float*)d_in[2];
    const float* emb         = (const float*)d_in[3];
    const float* w_ih        = (const float*)d_in[4];
    const float* w_hh        = (const float*)d_in[5];
    const float* b_ih        = (const float*)d_in[6];
    const float* b_hh        = (const float*)d_in[7];
    const float* concat_w    = (const float*)d_in[8];
    const float* concat_b    = (const float*)d_in[9];
    const float* owp         = (const float*)d_in[10];
    const float* obp         = (const float*)d_in[11];
    const float* owc         = (const float*)d_in[12];
    const float* obc         = (const float*)d_in[13];

    float* out        = (float*)d_out;
    float* out_hidden = out + (size_t)B * (VP + VC);   // [1,B,H]
    float* out_attn   = out_hidden + (size_t)B * H;    // [B,1,L]

    cudaFuncSetAttribute(gemm_part,  cudaFuncAttributeMaxDynamicSharedMemorySize, SM_GEMM);
    cudaFuncSetAttribute(logits_tf32, cudaFuncAttributeMaxDynamicSharedMemorySize, SM_GEMM);

    float* gatep; cudaGetSymbolAddress((void**)&gatep, g_gatep);
    float* xh;    cudaGetSymbolAddress((void**)&xh, g_xh);
    float* hc;    cudaGetSymbolAddress((void**)&hc, g_hc);
    float* cpart; cudaGetSymbolAddress((void**)&cpart, g_cpart);

    pack_xh_kernel<<<B, 256>>>(seq, last_hidden, emb);
    // GRU gates: 48 M-blocks (24 w_ih + 24 w_hh) x 2 K-splits
    gemm_part<<<dim3(48, GRU_SPLITS), 256, SM_GEMM>>>(
        w_ih, w_hh, xh, xh + (size_t)B * H, gatep,
        H, H / GRU_SPLITS, 24, GRU_ROWS);
    gru_gate_kernel<<<H / 4, 256>>>(last_hidden, b_ih, b_hh, out_hidden);
    flash2_kernel<<<dim3(B, CS), 256>>>(enc);          // 4th: profiled
    ctx_combine2_kernel<<<B, 256>>>();
    // concat: 8 M-blocks x 4 K-splits over K=2048
    gemm_part<<<dim3(8, CAT_SPLITS), 256, SM_GEMM>>>(
        concat_w, nullptr, hc, nullptr, cpart,
        2 * H, 2 * H / CAT_SPLITS, 0, CAT_ROWS);
    cat_reduce_kernel<<<H / 4, 256>>>(concat_b);
    logits_tf32<<<(VP + VC) / TVL, 256, SM_GEMM>>>(owp, obp, owc, obc, out);
    softmax_out_kernel<<<B, 256>>>(out_attn);
}